// round 1
// baseline (speedup 1.0000x reference)
#include <cuda_runtime.h>

#define TT 4096
#define DD 1024
#define FF 4096
#define EE 8
#define NROWS (TT * 2)

// ---- device scratch (static: no allocations allowed) ----
__device__ float g_act[(size_t)NROWS * FF];   // [2T, F] activations, ~134 MB
__device__ int   g_tokExp[TT * 2];
__device__ float g_tokW[TT * 2];
__device__ int   g_count[EE];
__device__ int   g_offset[EE];
__device__ int   g_cursor[EE];
__device__ int   g_rowTok[NROWS];
__device__ float g_rowW[NROWS];

// ------------------------------------------------------------------
// reset per-launch state
// ------------------------------------------------------------------
__global__ void reset_kernel() {
    int i = threadIdx.x;
    if (i < EE) g_count[i] = 0;
}

// ------------------------------------------------------------------
// router: logits -> top2 of softmax -> renormalized weights
// one block (128 threads) per token
// ------------------------------------------------------------------
__global__ void router_kernel(const float* __restrict__ x,
                              const float* __restrict__ gw,
                              const float* __restrict__ gb) {
    const int t   = blockIdx.x;
    const int tid = threadIdx.x;
    float acc[EE];
#pragma unroll
    for (int e = 0; e < EE; e++) acc[e] = 0.f;
    const float* xr = x + (size_t)t * DD;
    for (int d = tid; d < DD; d += 128) {
        float xv = xr[d];
#pragma unroll
        for (int e = 0; e < EE; e++) acc[e] += xv * gw[e * DD + d];
    }
    __shared__ float red[EE][128];
#pragma unroll
    for (int e = 0; e < EE; e++) red[e][tid] = acc[e];
    __syncthreads();
    for (int s = 64; s > 0; s >>= 1) {
        if (tid < s) {
#pragma unroll
            for (int e = 0; e < EE; e++) red[e][tid] += red[e][tid + s];
        }
        __syncthreads();
    }
    if (tid == 0) {
        float lg[EE];
        float mx = -1e30f;
#pragma unroll
        for (int e = 0; e < EE; e++) { lg[e] = red[e][0] + gb[e]; mx = fmaxf(mx, lg[e]); }
#pragma unroll
        for (int e = 0; e < EE; e++) lg[e] = expf(lg[e] - mx);
        // top-2 (softmax is monotonic in logits; renorm cancels denominator)
        int i1 = 0;
#pragma unroll
        for (int e = 1; e < EE; e++) if (lg[e] > lg[i1]) i1 = e;
        int i2 = (i1 == 0) ? 1 : 0;
#pragma unroll
        for (int e = 0; e < EE; e++) if (e != i2 && e != i1 && lg[e] > lg[i2]) i2 = e;
        float p1 = lg[i1], p2 = lg[i2];
        float inv = 1.f / (p1 + p2);
        g_tokExp[t * 2 + 0] = i1;  g_tokW[t * 2 + 0] = p1 * inv;
        g_tokExp[t * 2 + 1] = i2;  g_tokW[t * 2 + 1] = p2 * inv;
        atomicAdd(&g_count[i1], 1);
        atomicAdd(&g_count[i2], 1);
    }
}

// ------------------------------------------------------------------
// exclusive scan of counts (E=8 -> single thread)
// ------------------------------------------------------------------
__global__ void scan_kernel() {
    if (threadIdx.x == 0 && blockIdx.x == 0) {
        int off = 0;
#pragma unroll
        for (int e = 0; e < EE; e++) {
            g_offset[e] = off;
            g_cursor[e] = off;
            off += g_count[e];
        }
    }
}

// ------------------------------------------------------------------
// scatter tokens into per-expert contiguous row segments
// ------------------------------------------------------------------
__global__ void scatter_kernel() {
    int t = blockIdx.x * blockDim.x + threadIdx.x;
    if (t >= TT) return;
#pragma unroll
    for (int s = 0; s < 2; s++) {
        int e = g_tokExp[t * 2 + s];
        int p = atomicAdd(&g_cursor[e], 1);
        g_rowTok[p] = t;
        g_rowW[p]   = g_tokW[t * 2 + s];
    }
}

// ------------------------------------------------------------------
// GEMM1: act = silu(Xg @ w1[e]^T) * (Xg @ w3[e]^T)  (Xg = gathered rows)
// tile: M=128, N=64, K=16; 256 threads; 8x4 per-thread microtile x2
// grid: (F/64, T/128, E)
// ------------------------------------------------------------------
#define BS_PAD 72

__global__ void __launch_bounds__(256, 2)
gemm1_kernel(const float* __restrict__ x,
             const float* __restrict__ w1,
             const float* __restrict__ w3) {
    const int e    = blockIdx.z;
    const int cnt  = g_count[e];
    const int off  = g_offset[e];
    const int mB   = blockIdx.y * 128;
    if (mB >= cnt) return;
    const int rowEnd = off + cnt;
    const int nf0    = blockIdx.x * 64;

    __shared__ float As [16][128];
    __shared__ float Bs1[16][BS_PAD];
    __shared__ float Bs2[16][BS_PAD];

    const int tid = threadIdx.x;
    const int tm  = tid >> 4;          // 0..15
    const int tn  = tid & 15;          // 0..15
    const int m0  = tm * 8;
    const int n0  = tn * 4;

    float acc1[8][4], acc2[8][4];
#pragma unroll
    for (int i = 0; i < 8; i++)
#pragma unroll
        for (int j = 0; j < 4; j++) { acc1[i][j] = 0.f; acc2[i][j] = 0.f; }

    const float* w1e = w1 + (size_t)e * FF * DD;
    const float* w3e = w3 + (size_t)e * FF * DD;

    // B load mapping: kc = tid&3 (k-chunk of 4 floats), n = tid>>2 (0..63)
    const int bkc = tid & 3;
    const int bn  = tid >> 2;

    for (int k0 = 0; k0 < DD; k0 += 16) {
        // ---- load A (gathered x rows) ----
#pragma unroll
        for (int p = 0; p < 2; p++) {
            int idx = p * 256 + tid;
            int row = idx & 127;
            int kc  = idx >> 7;        // 0..3
            int gr  = off + mB + row;
            float4 v = make_float4(0.f, 0.f, 0.f, 0.f);
            if (gr < rowEnd) {
                int tok = g_rowTok[gr];
                v = *(const float4*)&x[(size_t)tok * DD + k0 + kc * 4];
            }
            As[kc * 4 + 0][row] = v.x;
            As[kc * 4 + 1][row] = v.y;
            As[kc * 4 + 2][row] = v.z;
            As[kc * 4 + 3][row] = v.w;
        }
        // ---- load B (w1, w3) ----
        {
            float4 v1 = *(const float4*)&w1e[(size_t)(nf0 + bn) * DD + k0 + bkc * 4];
            float4 v2 = *(const float4*)&w3e[(size_t)(nf0 + bn) * DD + k0 + bkc * 4];
            Bs1[bkc * 4 + 0][bn] = v1.x;  Bs1[bkc * 4 + 1][bn] = v1.y;
            Bs1[bkc * 4 + 2][bn] = v1.z;  Bs1[bkc * 4 + 3][bn] = v1.w;
            Bs2[bkc * 4 + 0][bn] = v2.x;  Bs2[bkc * 4 + 1][bn] = v2.y;
            Bs2[bkc * 4 + 2][bn] = v2.z;  Bs2[bkc * 4 + 3][bn] = v2.w;
        }
        __syncthreads();
#pragma unroll
        for (int k = 0; k < 16; k++) {
            float4 a0 = *(const float4*)&As[k][m0];
            float4 a1 = *(const float4*)&As[k][m0 + 4];
            float4 b1 = *(const float4*)&Bs1[k][n0];
            float4 b2 = *(const float4*)&Bs2[k][n0];
            float av[8] = {a0.x, a0.y, a0.z, a0.w, a1.x, a1.y, a1.z, a1.w};
            float bv1[4] = {b1.x, b1.y, b1.z, b1.w};
            float bv2[4] = {b2.x, b2.y, b2.z, b2.w};
#pragma unroll
            for (int i = 0; i < 8; i++)
#pragma unroll
                for (int j = 0; j < 4; j++) {
                    acc1[i][j] += av[i] * bv1[j];
                    acc2[i][j] += av[i] * bv2[j];
                }
        }
        __syncthreads();
    }

    // ---- epilogue: silu(h1)*h3 -> g_act ----
#pragma unroll
    for (int i = 0; i < 8; i++) {
        int gr = off + mB + m0 + i;
        if (gr < rowEnd) {
            float4 o;
            {
                float h = acc1[i][0];
                o.x = h * (1.f / (1.f + expf(-h))) * acc2[i][0];
                h = acc1[i][1];
                o.y = h * (1.f / (1.f + expf(-h))) * acc2[i][1];
                h = acc1[i][2];
                o.z = h * (1.f / (1.f + expf(-h))) * acc2[i][2];
                h = acc1[i][3];
                o.w = h * (1.f / (1.f + expf(-h))) * acc2[i][3];
            }
            *(float4*)&g_act[(size_t)gr * FF + nf0 + n0] = o;
        }
    }
}

// ------------------------------------------------------------------
// GEMM2: out[tok] += w * (act @ w2[e]^T)
// tile: M=128, N=64, K=16; grid: (D/64, T/128, E)
// ------------------------------------------------------------------
__global__ void __launch_bounds__(256, 2)
gemm2_kernel(const float* __restrict__ w2,
             float* __restrict__ out) {
    const int e    = blockIdx.z;
    const int cnt  = g_count[e];
    const int off  = g_offset[e];
    const int mB   = blockIdx.y * 128;
    if (mB >= cnt) return;
    const int rowEnd = off + cnt;
    const int nd0    = blockIdx.x * 64;

    __shared__ float As[16][128];
    __shared__ float Bs[16][BS_PAD];

    const int tid = threadIdx.x;
    const int tm  = tid >> 4;
    const int tn  = tid & 15;
    const int m0  = tm * 8;
    const int n0  = tn * 4;

    float acc[8][4];
#pragma unroll
    for (int i = 0; i < 8; i++)
#pragma unroll
        for (int j = 0; j < 4; j++) acc[i][j] = 0.f;

    const float* w2e = w2 + (size_t)e * DD * FF;
    const int bkc = tid & 3;
    const int bn  = tid >> 2;

    for (int k0 = 0; k0 < FF; k0 += 16) {
        // ---- load A (contiguous rows of g_act) ----
#pragma unroll
        for (int p = 0; p < 2; p++) {
            int idx = p * 256 + tid;
            int row = idx & 127;
            int kc  = idx >> 7;
            int gr  = off + mB + row;
            float4 v = make_float4(0.f, 0.f, 0.f, 0.f);
            if (gr < rowEnd)
                v = *(const float4*)&g_act[(size_t)gr * FF + k0 + kc * 4];
            As[kc * 4 + 0][row] = v.x;
            As[kc * 4 + 1][row] = v.y;
            As[kc * 4 + 2][row] = v.z;
            As[kc * 4 + 3][row] = v.w;
        }
        // ---- load B (w2[e], [D, F] row-major) ----
        {
            float4 v = *(const float4*)&w2e[(size_t)(nd0 + bn) * FF + k0 + bkc * 4];
            Bs[bkc * 4 + 0][bn] = v.x;  Bs[bkc * 4 + 1][bn] = v.y;
            Bs[bkc * 4 + 2][bn] = v.z;  Bs[bkc * 4 + 3][bn] = v.w;
        }
        __syncthreads();
#pragma unroll
        for (int k = 0; k < 16; k++) {
            float4 a0 = *(const float4*)&As[k][m0];
            float4 a1 = *(const float4*)&As[k][m0 + 4];
            float4 b  = *(const float4*)&Bs[k][n0];
            float av[8] = {a0.x, a0.y, a0.z, a0.w, a1.x, a1.y, a1.z, a1.w};
            float bv[4] = {b.x, b.y, b.z, b.w};
#pragma unroll
            for (int i = 0; i < 8; i++)
#pragma unroll
                for (int j = 0; j < 4; j++)
                    acc[i][j] += av[i] * bv[j];
        }
        __syncthreads();
    }

    // ---- epilogue: weighted atomic combine (exactly 2 adds/elem, commutative) ----
#pragma unroll
    for (int i = 0; i < 8; i++) {
        int gr = off + mB + m0 + i;
        if (gr < rowEnd) {
            int   tok = g_rowTok[gr];
            float w   = g_rowW[gr];
            float* op = &out[(size_t)tok * DD + nd0 + n0];
            atomicAdd(op + 0, w * acc[i][0]);
            atomicAdd(op + 1, w * acc[i][1]);
            atomicAdd(op + 2, w * acc[i][2]);
            atomicAdd(op + 3, w * acc[i][3]);
        }
    }
}

// ------------------------------------------------------------------
extern "C" void kernel_launch(void* const* d_in, const int* in_sizes, int n_in,
                              void* d_out, int out_size) {
    const float* x   = (const float*)d_in[0];   // [T, D]
    const float* gw  = (const float*)d_in[1];   // [E, D]
    const float* gb  = (const float*)d_in[2];   // [E]
    const float* w1  = (const float*)d_in[3];   // [E, F, D]
    const float* w3  = (const float*)d_in[4];   // [E, F, D]
    const float* w2  = (const float*)d_in[5];   // [E, D, F]
    float* out = (float*)d_out;                 // [T, D]

    cudaMemsetAsync(out, 0, (size_t)out_size * sizeof(float), 0);
    reset_kernel<<<1, 32>>>();
    router_kernel<<<TT, 128>>>(x, gw, gb);
    scan_kernel<<<1, 32>>>();
    scatter_kernel<<<(TT + 255) / 256, 256>>>();

    dim3 g1(FF / 64, TT / 128, EE);
    gemm1_kernel<<<g1, 256>>>(x, w1, w3);
    dim3 g2(DD / 64, TT / 128, EE);
    gemm2_kernel<<<g2, 256>>>(w2, out);
}

// round 3
// speedup vs baseline: 2.2689x; 2.2689x over previous
#include <cuda_runtime.h>
#include <cuda_bf16.h>

#define TT 4096
#define DD 1024
#define FF 4096
#define EE 8
#define NROWS (TT * 2)
#define NW   (EE * FF * DD)

typedef unsigned int u32;

// ================= device scratch (static) =================
__device__ __nv_bfloat16 g_xhi[TT * DD], g_xlo[TT * DD];
__device__ __nv_bfloat16 g_w1hi[NW], g_w1lo[NW];
__device__ __nv_bfloat16 g_w3hi[NW], g_w3lo[NW];
__device__ __nv_bfloat16 g_w2hi[NW], g_w2lo[NW];
__device__ __nv_bfloat16 g_acthi[(size_t)NROWS * FF], g_actlo[(size_t)NROWS * FF];

__device__ int   g_tokExp[TT * 2];
__device__ float g_tokW[TT * 2];
__device__ int   g_count[EE];
__device__ int   g_offset[EE];
__device__ int   g_cursor[EE];
__device__ int   g_rowTok[NROWS];
__device__ float g_rowW[NROWS];

// ================= PTX helpers (sm_80-generic only) =================
__device__ __forceinline__ u32 smem_u32(const void* p) {
    u32 a;
    asm("{ .reg .u64 t; cvta.to.shared.u64 t, %1; cvt.u32.u64 %0, t; }" : "=r"(a) : "l"(p));
    return a;
}
__device__ __forceinline__ void cp16(u32 dst, const void* src) {
    asm volatile("cp.async.cg.shared.global [%0], [%1], 16;" :: "r"(dst), "l"(src));
}
__device__ __forceinline__ void cp_commit() {
    asm volatile("cp.async.commit_group;" ::: "memory");
}
__device__ __forceinline__ void cp_wait1() {
    asm volatile("cp.async.wait_group 1;" ::: "memory");
}
__device__ __forceinline__ void ldsm4(u32 addr, u32* r) {
    asm volatile("ldmatrix.sync.aligned.m8n8.x4.shared.b16 {%0,%1,%2,%3}, [%4];"
        : "=r"(r[0]), "=r"(r[1]), "=r"(r[2]), "=r"(r[3]) : "r"(addr));
}
__device__ __forceinline__ void mma16816(float* d, const u32* a, const u32* b) {
    asm volatile(
        "mma.sync.aligned.m16n8k16.row.col.f32.bf16.bf16.f32 "
        "{%0,%1,%2,%3}, {%4,%5,%6,%7}, {%8,%9}, {%0,%1,%2,%3};"
        : "+f"(d[0]), "+f"(d[1]), "+f"(d[2]), "+f"(d[3])
        : "r"(a[0]), "r"(a[1]), "r"(a[2]), "r"(a[3]), "r"(b[0]), "r"(b[1]));
}

#define KT     32
#define PITCH  40                    // bf16 elems per smem row (80B: conflict-free)
#define TILE_B (128 * PITCH * 2)     // 10240 B per 128xKT bf16 tile

// ================= routing =================
__global__ void reset_kernel() {
    if (threadIdx.x < EE) g_count[threadIdx.x] = 0;
}

__global__ void router_kernel(const float* __restrict__ x,
                              const float* __restrict__ gw,
                              const float* __restrict__ gb) {
    const int t = blockIdx.x, tid = threadIdx.x;
    float acc[EE];
#pragma unroll
    for (int e = 0; e < EE; e++) acc[e] = 0.f;
    const float* xr = x + (size_t)t * DD;
    for (int d = tid; d < DD; d += 128) {
        float xv = xr[d];
#pragma unroll
        for (int e = 0; e < EE; e++) acc[e] += xv * gw[e * DD + d];
    }
    __shared__ float red[EE][128];
#pragma unroll
    for (int e = 0; e < EE; e++) red[e][tid] = acc[e];
    __syncthreads();
    for (int s = 64; s > 0; s >>= 1) {
        if (tid < s) {
#pragma unroll
            for (int e = 0; e < EE; e++) red[e][tid] += red[e][tid + s];
        }
        __syncthreads();
    }
    if (tid == 0) {
        float lg[EE]; float mx = -1e30f;
#pragma unroll
        for (int e = 0; e < EE; e++) { lg[e] = red[e][0] + gb[e]; mx = fmaxf(mx, lg[e]); }
#pragma unroll
        for (int e = 0; e < EE; e++) lg[e] = expf(lg[e] - mx);
        int i1 = 0;
#pragma unroll
        for (int e = 1; e < EE; e++) if (lg[e] > lg[i1]) i1 = e;
        int i2 = (i1 == 0) ? 1 : 0;
#pragma unroll
        for (int e = 0; e < EE; e++) if (e != i2 && e != i1 && lg[e] > lg[i2]) i2 = e;
        float p1 = lg[i1], p2 = lg[i2], inv = 1.f / (p1 + p2);
        g_tokExp[t * 2 + 0] = i1; g_tokW[t * 2 + 0] = p1 * inv;
        g_tokExp[t * 2 + 1] = i2; g_tokW[t * 2 + 1] = p2 * inv;
        atomicAdd(&g_count[i1], 1);
        atomicAdd(&g_count[i2], 1);
    }
}

__global__ void scan_kernel() {
    if (threadIdx.x == 0 && blockIdx.x == 0) {
        int off = 0;
#pragma unroll
        for (int e = 0; e < EE; e++) { g_offset[e] = off; g_cursor[e] = off; off += g_count[e]; }
    }
}

__global__ void scatter_kernel() {
    int t = blockIdx.x * blockDim.x + threadIdx.x;
    if (t >= TT) return;
#pragma unroll
    for (int s = 0; s < 2; s++) {
        int e = g_tokExp[t * 2 + s];
        int p = atomicAdd(&g_cursor[e], 1);
        g_rowTok[p] = t;
        g_rowW[p]   = g_tokW[t * 2 + s];
    }
}

// ================= fp32 -> bf16 hi/lo split =================
__global__ void split_kernel(const float* __restrict__ src,
                             __nv_bfloat16* __restrict__ hi,
                             __nv_bfloat16* __restrict__ lo, int n4) {
    int i = blockIdx.x * blockDim.x + threadIdx.x;
    if (i >= n4) return;
    float4 v = ((const float4*)src)[i];
    __nv_bfloat162 h01, h23, l01, l23;
    h01.x = __float2bfloat16(v.x); l01.x = __float2bfloat16(v.x - __bfloat162float(h01.x));
    h01.y = __float2bfloat16(v.y); l01.y = __float2bfloat16(v.y - __bfloat162float(h01.y));
    h23.x = __float2bfloat16(v.z); l23.x = __float2bfloat16(v.z - __bfloat162float(h23.x));
    h23.y = __float2bfloat16(v.w); l23.y = __float2bfloat16(v.w - __bfloat162float(h23.y));
    ((uint2*)hi)[i] = make_uint2(*(u32*)&h01, *(u32*)&h23);
    ((uint2*)lo)[i] = make_uint2(*(u32*)&l01, *(u32*)&l23);
}

// ================= GEMM1: act = silu(Xg@w1^T)*(Xg@w3^T), bf16x3 HMMA ===========
// block 128x128, K-stage 32, 8 warps (4m x 2n), warp tile 32x64
#define G1_SMEM (512 + 2 * 6 * TILE_B)   // 123392

__global__ void __launch_bounds__(256, 1)
gemm1_mma() {
    extern __shared__ char smem[];
    const int e   = blockIdx.z;
    const int cnt = g_count[e];
    const int off = g_offset[e];
    const int mB  = blockIdx.y * 128;
    if (mB >= cnt) return;
    const int valid = min(128, cnt - mB);
    const int nf0   = blockIdx.x * 128;
    const int tid   = threadIdx.x;
    const int wid   = tid >> 5, lane = tid & 31;

    int* tokSm = (int*)smem;
    if (tid < 128) tokSm[tid] = g_rowTok[off + mB + min(tid, valid - 1)];
    __syncthreads();

    const u32 sb = smem_u32(smem);
    const u32 stb[2] = { sb + 512, sb + 512 + 6 * TILE_B };
    const size_t wbase = (size_t)e * FF * DD + (size_t)nf0 * DD;

    // per-thread load mapping: chunk i -> row=i>>2, ch=i&3 (16B each)
    const int lrow = tid >> 2, lch = tid & 3;
    const u32 so0 = (u32)(lrow * PITCH + lch * 8) * 2;
    const u32 so1 = (u32)((lrow + 64) * PITCH + lch * 8) * 2;
    const int tokA = tokSm[lrow], tokB = tokSm[lrow + 64];

    auto load_stage = [&](int s, int k0) {
        u32 st = stb[s];
        const size_t xa = (size_t)tokA * DD + k0 + lch * 8;
        const size_t xb = (size_t)tokB * DD + k0 + lch * 8;
        cp16(st + so0,          &g_xhi[xa]);
        cp16(st + so1,          &g_xhi[xb]);
        cp16(st + TILE_B + so0, &g_xlo[xa]);
        cp16(st + TILE_B + so1, &g_xlo[xb]);
        const size_t ga = wbase + (size_t)lrow * DD + k0 + lch * 8;
        const size_t gb2 = wbase + (size_t)(lrow + 64) * DD + k0 + lch * 8;
        cp16(st + 2 * TILE_B + so0, &g_w1hi[ga]);
        cp16(st + 2 * TILE_B + so1, &g_w1hi[gb2]);
        cp16(st + 3 * TILE_B + so0, &g_w1lo[ga]);
        cp16(st + 3 * TILE_B + so1, &g_w1lo[gb2]);
        cp16(st + 4 * TILE_B + so0, &g_w3hi[ga]);
        cp16(st + 4 * TILE_B + so1, &g_w3hi[gb2]);
        cp16(st + 5 * TILE_B + so0, &g_w3lo[ga]);
        cp16(st + 5 * TILE_B + so1, &g_w3lo[gb2]);
    };

    // ldmatrix lane address components
    const int m_w = (wid >> 1) * 32, n_w = (wid & 1) * 64;
    const int lmat = lane >> 3, lr = lane & 7;
    const int aRow = m_w + (lmat & 1) * 8 + lr;
    const int aCol = (lmat >> 1) * 8;
    const int bRow = n_w + (lmat >> 1) * 8 + lr;
    const int bCol = (lmat & 1) * 8;

    float acc1[2][8][4], acc2[2][8][4];
#pragma unroll
    for (int mt = 0; mt < 2; mt++)
#pragma unroll
        for (int nt = 0; nt < 8; nt++)
#pragma unroll
            for (int q = 0; q < 4; q++) { acc1[mt][nt][q] = 0.f; acc2[mt][nt][q] = 0.f; }

    load_stage(0, 0);  cp_commit();
    load_stage(1, KT); cp_commit();

    const int NK = DD / KT;   // 32
    for (int kt = 0; kt < NK; kt++) {
        const int s = kt & 1;
        cp_wait1();
        __syncthreads();
        const u32 st = stb[s];
#pragma unroll
        for (int k16 = 0; k16 < KT; k16 += 16) {
            u32 aH[2][4], aL[2][4];
#pragma unroll
            for (int mt = 0; mt < 2; mt++) {
                u32 ao = (u32)((aRow + mt * 16) * PITCH + k16 + aCol) * 2;
                ldsm4(st + ao, aH[mt]);
                ldsm4(st + TILE_B + ao, aL[mt]);
            }
#pragma unroll
            for (int p = 0; p < 4; p++) {
                u32 bo = (u32)((bRow + p * 16) * PITCH + k16 + bCol) * 2;
                u32 b1h[4], b1l[4], b3h[4], b3l[4];
                ldsm4(st + 2 * TILE_B + bo, b1h);
                ldsm4(st + 3 * TILE_B + bo, b1l);
                ldsm4(st + 4 * TILE_B + bo, b3h);
                ldsm4(st + 5 * TILE_B + bo, b3l);
#pragma unroll
                for (int mt = 0; mt < 2; mt++)
#pragma unroll
                    for (int q = 0; q < 2; q++) {
                        int nt = p * 2 + q;
                        mma16816(acc1[mt][nt], aH[mt], &b1h[q * 2]);
                        mma16816(acc1[mt][nt], aH[mt], &b1l[q * 2]);
                        mma16816(acc1[mt][nt], aL[mt], &b1h[q * 2]);
                        mma16816(acc2[mt][nt], aH[mt], &b3h[q * 2]);
                        mma16816(acc2[mt][nt], aH[mt], &b3l[q * 2]);
                        mma16816(acc2[mt][nt], aL[mt], &b3h[q * 2]);
                    }
            }
        }
        __syncthreads();
        if (kt + 2 < NK) load_stage(s, (kt + 2) * KT);
        cp_commit();
    }

    // epilogue: silu(h1)*h3 -> bf16 hi/lo -> global
    u32* outHi = (u32*)g_acthi;
    u32* outLo = (u32*)g_actlo;
#pragma unroll
    for (int mt = 0; mt < 2; mt++)
#pragma unroll
        for (int rh = 0; rh < 2; rh++) {
            int rowl = m_w + mt * 16 + rh * 8 + (lane >> 2);
            if (rowl < valid) {
                size_t base = (size_t)(off + mB + rowl) * FF + nf0;
#pragma unroll
                for (int nt = 0; nt < 8; nt++) {
                    float h0 = acc1[mt][nt][rh * 2 + 0];
                    float h1 = acc1[mt][nt][rh * 2 + 1];
                    float a0 = h0 * (1.f / (1.f + __expf(-h0))) * acc2[mt][nt][rh * 2 + 0];
                    float a1 = h1 * (1.f / (1.f + __expf(-h1))) * acc2[mt][nt][rh * 2 + 1];
                    __nv_bfloat162 hh, ll;
                    hh.x = __float2bfloat16(a0); ll.x = __float2bfloat16(a0 - __bfloat162float(hh.x));
                    hh.y = __float2bfloat16(a1); ll.y = __float2bfloat16(a1 - __bfloat162float(hh.y));
                    size_t gi = (base + n_w + nt * 8 + (lane & 3) * 2) >> 1;
                    outHi[gi] = *(u32*)&hh;
                    outLo[gi] = *(u32*)&ll;
                }
            }
        }
}

// ================= GEMM2: out += w * (act @ w2^T), bf16x3 HMMA =================
#define G2_SMEM (512 + 2 * 4 * TILE_B)   // 82432

__global__ void __launch_bounds__(256, 1)
gemm2_mma(float* __restrict__ out) {
    extern __shared__ char smem[];
    const int e   = blockIdx.z;
    const int cnt = g_count[e];
    const int off = g_offset[e];
    const int mB  = blockIdx.y * 128;
    if (mB >= cnt) return;
    const int valid = min(128, cnt - mB);
    const int nd0   = blockIdx.x * 128;
    const int tid   = threadIdx.x;
    const int wid   = tid >> 5, lane = tid & 31;

    const u32 sb = smem_u32(smem);
    const u32 stb[2] = { sb + 512, sb + 512 + 4 * TILE_B };
    const size_t wbase = (size_t)e * DD * FF + (size_t)nd0 * FF;

    const int lrow = tid >> 2, lch = tid & 3;
    const u32 so0 = (u32)(lrow * PITCH + lch * 8) * 2;
    const u32 so1 = (u32)((lrow + 64) * PITCH + lch * 8) * 2;
    const int arow0 = off + mB + min(lrow, valid - 1);
    const int arow1 = off + mB + min(lrow + 64, valid - 1);

    auto load_stage = [&](int s, int k0) {
        u32 st = stb[s];
        const size_t aa = (size_t)arow0 * FF + k0 + lch * 8;
        const size_t ab = (size_t)arow1 * FF + k0 + lch * 8;
        cp16(st + so0,          &g_acthi[aa]);
        cp16(st + so1,          &g_acthi[ab]);
        cp16(st + TILE_B + so0, &g_actlo[aa]);
        cp16(st + TILE_B + so1, &g_actlo[ab]);
        const size_t ga = wbase + (size_t)lrow * FF + k0 + lch * 8;
        const size_t gb2 = wbase + (size_t)(lrow + 64) * FF + k0 + lch * 8;
        cp16(st + 2 * TILE_B + so0, &g_w2hi[ga]);
        cp16(st + 2 * TILE_B + so1, &g_w2hi[gb2]);
        cp16(st + 3 * TILE_B + so0, &g_w2lo[ga]);
        cp16(st + 3 * TILE_B + so1, &g_w2lo[gb2]);
    };

    const int m_w = (wid >> 1) * 32, n_w = (wid & 1) * 64;
    const int lmat = lane >> 3, lr = lane & 7;
    const int aRow = m_w + (lmat & 1) * 8 + lr;
    const int aCol = (lmat >> 1) * 8;
    const int bRow = n_w + (lmat >> 1) * 8 + lr;
    const int bCol = (lmat & 1) * 8;

    float acc[2][8][4];
#pragma unroll
    for (int mt = 0; mt < 2; mt++)
#pragma unroll
        for (int nt = 0; nt < 8; nt++)
#pragma unroll
            for (int q = 0; q < 4; q++) acc[mt][nt][q] = 0.f;

    load_stage(0, 0);  cp_commit();
    load_stage(1, KT); cp_commit();

    const int NK = FF / KT;   // 128
    for (int kt = 0; kt < NK; kt++) {
        const int s = kt & 1;
        cp_wait1();
        __syncthreads();
        const u32 st = stb[s];
#pragma unroll
        for (int k16 = 0; k16 < KT; k16 += 16) {
            u32 aH[2][4], aL[2][4];
#pragma unroll
            for (int mt = 0; mt < 2; mt++) {
                u32 ao = (u32)((aRow + mt * 16) * PITCH + k16 + aCol) * 2;
                ldsm4(st + ao, aH[mt]);
                ldsm4(st + TILE_B + ao, aL[mt]);
            }
#pragma unroll
            for (int p = 0; p < 4; p++) {
                u32 bo = (u32)((bRow + p * 16) * PITCH + k16 + bCol) * 2;
                u32 bh[4], bl[4];
                ldsm4(st + 2 * TILE_B + bo, bh);
                ldsm4(st + 3 * TILE_B + bo, bl);
#pragma unroll
                for (int mt = 0; mt < 2; mt++)
#pragma unroll
                    for (int q = 0; q < 2; q++) {
                        int nt = p * 2 + q;
                        mma16816(acc[mt][nt], aH[mt], &bh[q * 2]);
                        mma16816(acc[mt][nt], aH[mt], &bl[q * 2]);
                        mma16816(acc[mt][nt], aL[mt], &bh[q * 2]);
                    }
            }
        }
        __syncthreads();
        if (kt + 2 < NK) load_stage(s, (kt + 2) * KT);
        cp_commit();
    }

    // epilogue: weighted atomic combine
#pragma unroll
    for (int mt = 0; mt < 2; mt++)
#pragma unroll
        for (int rh = 0; rh < 2; rh++) {
            int rowl = m_w + mt * 16 + rh * 8 + (lane >> 2);
            if (rowl < valid) {
                int gr = off + mB + rowl;
                int tok = g_rowTok[gr];
                float w = g_rowW[gr];
                float* op = &out[(size_t)tok * DD + nd0];
#pragma unroll
                for (int nt = 0; nt < 8; nt++) {
                    int c = n_w + nt * 8 + (lane & 3) * 2;
                    atomicAdd(op + c,     w * acc[mt][nt][rh * 2 + 0]);
                    atomicAdd(op + c + 1, w * acc[mt][nt][rh * 2 + 1]);
                }
            }
        }
}

// ================= host =================
extern "C" void kernel_launch(void* const* d_in, const int* in_sizes, int n_in,
                              void* d_out, int out_size) {
    const float* x  = (const float*)d_in[0];
    const float* gw = (const float*)d_in[1];
    const float* gb = (const float*)d_in[2];
    const float* w1 = (const float*)d_in[3];
    const float* w3 = (const float*)d_in[4];
    const float* w2 = (const float*)d_in[5];
    float* out = (float*)d_out;

    cudaFuncSetAttribute(gemm1_mma, cudaFuncAttributeMaxDynamicSharedMemorySize, G1_SMEM);
    cudaFuncSetAttribute(gemm2_mma, cudaFuncAttributeMaxDynamicSharedMemorySize, G2_SMEM);

    __nv_bfloat16 *xhi, *xlo, *w1hi, *w1lo, *w3hi, *w3lo, *w2hi, *w2lo;
    cudaGetSymbolAddress((void**)&xhi,  g_xhi);  cudaGetSymbolAddress((void**)&xlo,  g_xlo);
    cudaGetSymbolAddress((void**)&w1hi, g_w1hi); cudaGetSymbolAddress((void**)&w1lo, g_w1lo);
    cudaGetSymbolAddress((void**)&w3hi, g_w3hi); cudaGetSymbolAddress((void**)&w3lo, g_w3lo);
    cudaGetSymbolAddress((void**)&w2hi, g_w2hi); cudaGetSymbolAddress((void**)&w2lo, g_w2lo);

    cudaMemsetAsync(out, 0, (size_t)out_size * sizeof(float), 0);
    reset_kernel<<<1, 32>>>();
    router_kernel<<<TT, 128>>>(x, gw, gb);
    scan_kernel<<<1, 32>>>();
    scatter_kernel<<<(TT + 255) / 256, 256>>>();

    split_kernel<<<(TT * DD / 4 + 255) / 256, 256>>>(x, xhi, xlo, TT * DD / 4);
    split_kernel<<<(NW / 4 + 255) / 256, 256>>>(w1, w1hi, w1lo, NW / 4);
    split_kernel<<<(NW / 4 + 255) / 256, 256>>>(w3, w3hi, w3lo, NW / 4);
    split_kernel<<<(NW / 4 + 255) / 256, 256>>>(w2, w2hi, w2lo, NW / 4);

    dim3 g1(FF / 128, 32, EE);
    gemm1_mma<<<g1, 256, G1_SMEM>>>();
    dim3 g2(DD / 128, 32, EE);
    gemm2_mma<<<g2, 256, G2_SMEM>>>(out);
}

// round 4
// speedup vs baseline: 2.3396x; 1.0312x over previous
#include <cuda_runtime.h>
#include <cuda_bf16.h>

#define TT 4096
#define DD 1024
#define FF 4096
#define EE 8
#define NROWS (TT * 2)
#define NW   (EE * FF * DD)

typedef unsigned int u32;

// ================= device scratch (static) =================
__device__ __nv_bfloat16 g_xhi[TT * DD], g_xlo[TT * DD];
__device__ __nv_bfloat16 g_w1hi[NW], g_w1lo[NW];
__device__ __nv_bfloat16 g_w3hi[NW], g_w3lo[NW];
__device__ __nv_bfloat16 g_w2hi[NW], g_w2lo[NW];
__device__ __nv_bfloat16 g_acthi[(size_t)NROWS * FF], g_actlo[(size_t)NROWS * FF];

__device__ int   g_tokExp[TT * 2];
__device__ float g_tokW[TT * 2];
__device__ int   g_count[EE];
__device__ int   g_offset[EE];
__device__ int   g_cursor[EE];
__device__ int   g_rowTok[NROWS];
__device__ float g_rowW[NROWS];

// ================= PTX helpers (sm_80-generic only) =================
__device__ __forceinline__ u32 smem_u32(const void* p) {
    u32 a;
    asm("{ .reg .u64 t; cvta.to.shared.u64 t, %1; cvt.u32.u64 %0, t; }" : "=r"(a) : "l"(p));
    return a;
}
__device__ __forceinline__ void cp16(u32 dst, const void* src) {
    asm volatile("cp.async.cg.shared.global [%0], [%1], 16;" :: "r"(dst), "l"(src));
}
__device__ __forceinline__ void cp_commit() {
    asm volatile("cp.async.commit_group;" ::: "memory");
}
__device__ __forceinline__ void cp_wait1() {
    asm volatile("cp.async.wait_group 1;" ::: "memory");
}
__device__ __forceinline__ void cp_wait2() {
    asm volatile("cp.async.wait_group 2;" ::: "memory");
}
__device__ __forceinline__ void ldsm4(u32 addr, u32* r) {
    asm volatile("ldmatrix.sync.aligned.m8n8.x4.shared.b16 {%0,%1,%2,%3}, [%4];"
        : "=r"(r[0]), "=r"(r[1]), "=r"(r[2]), "=r"(r[3]) : "r"(addr));
}
__device__ __forceinline__ void mma16816(float* d, const u32* a, const u32* b) {
    asm volatile(
        "mma.sync.aligned.m16n8k16.row.col.f32.bf16.bf16.f32 "
        "{%0,%1,%2,%3}, {%4,%5,%6,%7}, {%8,%9}, {%0,%1,%2,%3};"
        : "+f"(d[0]), "+f"(d[1]), "+f"(d[2]), "+f"(d[3])
        : "r"(a[0]), "r"(a[1]), "r"(a[2]), "r"(a[3]), "r"(b[0]), "r"(b[1]));
}

#define KT     32
#define PITCH  40                    // bf16 elems per smem row (80B: conflict-free)
#define TILE_B (128 * PITCH * 2)     // 10240 B per 128xKT bf16 tile

// ================= fused split (+reset) =================
#define XC  (TT * DD / 4)
#define WC  (NW / 4)
__global__ void __launch_bounds__(256)
split_all_kernel(const float* __restrict__ x,  const float* __restrict__ w1,
                 const float* __restrict__ w3, const float* __restrict__ w2) {
    if (blockIdx.x == 0 && threadIdx.x < EE) g_count[threadIdx.x] = 0;
    size_t i = (size_t)blockIdx.x * 256 + threadIdx.x;
    const float* src;
    __nv_bfloat16 *hi, *lo;
    if (i < XC)               { src = x;  hi = g_xhi;  lo = g_xlo; }
    else if (i < XC + WC)     { src = w1; hi = g_w1hi; lo = g_w1lo; i -= XC; }
    else if (i < XC + 2 * WC) { src = w3; hi = g_w3hi; lo = g_w3lo; i -= XC + WC; }
    else if (i < XC + 3 * WC) { src = w2; hi = g_w2hi; lo = g_w2lo; i -= XC + 2 * WC; }
    else return;
    float4 v = ((const float4*)src)[i];
    __nv_bfloat162 h01, h23, l01, l23;
    h01.x = __float2bfloat16(v.x); l01.x = __float2bfloat16(v.x - __bfloat162float(h01.x));
    h01.y = __float2bfloat16(v.y); l01.y = __float2bfloat16(v.y - __bfloat162float(h01.y));
    h23.x = __float2bfloat16(v.z); l23.x = __float2bfloat16(v.z - __bfloat162float(h23.x));
    h23.y = __float2bfloat16(v.w); l23.y = __float2bfloat16(v.w - __bfloat162float(h23.y));
    ((uint2*)hi)[i] = make_uint2(*(u32*)&h01, *(u32*)&h23);
    ((uint2*)lo)[i] = make_uint2(*(u32*)&l01, *(u32*)&l23);
}

// ================= router =================
__global__ void router_kernel(const float* __restrict__ x,
                              const float* __restrict__ gw,
                              const float* __restrict__ gb) {
    const int t = blockIdx.x, tid = threadIdx.x;
    float acc[EE];
#pragma unroll
    for (int e = 0; e < EE; e++) acc[e] = 0.f;
    const float* xr = x + (size_t)t * DD;
    for (int d = tid; d < DD; d += 128) {
        float xv = xr[d];
#pragma unroll
        for (int e = 0; e < EE; e++) acc[e] += xv * gw[e * DD + d];
    }
    __shared__ float red[EE][128];
#pragma unroll
    for (int e = 0; e < EE; e++) red[e][tid] = acc[e];
    __syncthreads();
    for (int s = 64; s > 0; s >>= 1) {
        if (tid < s) {
#pragma unroll
            for (int e = 0; e < EE; e++) red[e][tid] += red[e][tid + s];
        }
        __syncthreads();
    }
    if (tid == 0) {
        float lg[EE]; float mx = -1e30f;
#pragma unroll
        for (int e = 0; e < EE; e++) { lg[e] = red[e][0] + gb[e]; mx = fmaxf(mx, lg[e]); }
#pragma unroll
        for (int e = 0; e < EE; e++) lg[e] = expf(lg[e] - mx);
        int i1 = 0;
#pragma unroll
        for (int e = 1; e < EE; e++) if (lg[e] > lg[i1]) i1 = e;
        int i2 = (i1 == 0) ? 1 : 0;
#pragma unroll
        for (int e = 0; e < EE; e++) if (e != i2 && e != i1 && lg[e] > lg[i2]) i2 = e;
        float p1 = lg[i1], p2 = lg[i2], inv = 1.f / (p1 + p2);
        g_tokExp[t * 2 + 0] = i1; g_tokW[t * 2 + 0] = p1 * inv;
        g_tokExp[t * 2 + 1] = i2; g_tokW[t * 2 + 1] = p2 * inv;
        atomicAdd(&g_count[i1], 1);
        atomicAdd(&g_count[i2], 1);
    }
}

// ================= fused scan + scatter (single block) =================
__global__ void scanscatter_kernel() {
    const int tid = threadIdx.x;
    if (tid == 0) {
        int off = 0;
#pragma unroll
        for (int e = 0; e < EE; e++) { g_offset[e] = off; g_cursor[e] = off; off += g_count[e]; }
    }
    __syncthreads();
    for (int t = tid; t < TT; t += 256) {
#pragma unroll
        for (int s = 0; s < 2; s++) {
            int e = g_tokExp[t * 2 + s];
            int p = atomicAdd(&g_cursor[e], 1);
            g_rowTok[p] = t;
            g_rowW[p]   = g_tokW[t * 2 + s];
        }
    }
}

// ================= GEMM1: act = silu(Xg@w1^T)*(Xg@w3^T), bf16x3 HMMA ===========
// block 128x128, K-stage 32, 3-stage cp.async pipeline
#define G1_SMEM (512 + 3 * 6 * TILE_B)   // 184832

__global__ void __launch_bounds__(256, 1)
gemm1_mma() {
    extern __shared__ char smem[];
    const int e   = blockIdx.z;
    const int cnt = g_count[e];
    const int off = g_offset[e];
    const int mB  = blockIdx.y * 128;
    if (mB >= cnt) return;
    const int valid = min(128, cnt - mB);
    const int nf0   = blockIdx.x * 128;
    const int tid   = threadIdx.x;
    const int wid   = tid >> 5, lane = tid & 31;

    int* tokSm = (int*)smem;
    if (tid < 128) tokSm[tid] = g_rowTok[off + mB + min(tid, valid - 1)];
    __syncthreads();

    const u32 sb = smem_u32(smem);
    const size_t wbase = (size_t)e * FF * DD + (size_t)nf0 * DD;

    const int lrow = tid >> 2, lch = tid & 3;
    const u32 so0 = (u32)(lrow * PITCH + lch * 8) * 2;
    const u32 so1 = (u32)((lrow + 64) * PITCH + lch * 8) * 2;
    const int tokA = tokSm[lrow], tokB = tokSm[lrow + 64];

    auto load_stage = [&](int s, int k0) {
        u32 st = sb + 512 + s * 6 * TILE_B;
        const size_t xa = (size_t)tokA * DD + k0 + lch * 8;
        const size_t xb = (size_t)tokB * DD + k0 + lch * 8;
        cp16(st + so0,          &g_xhi[xa]);
        cp16(st + so1,          &g_xhi[xb]);
        cp16(st + TILE_B + so0, &g_xlo[xa]);
        cp16(st + TILE_B + so1, &g_xlo[xb]);
        const size_t ga  = wbase + (size_t)lrow * DD + k0 + lch * 8;
        const size_t gb2 = wbase + (size_t)(lrow + 64) * DD + k0 + lch * 8;
        cp16(st + 2 * TILE_B + so0, &g_w1hi[ga]);
        cp16(st + 2 * TILE_B + so1, &g_w1hi[gb2]);
        cp16(st + 3 * TILE_B + so0, &g_w1lo[ga]);
        cp16(st + 3 * TILE_B + so1, &g_w1lo[gb2]);
        cp16(st + 4 * TILE_B + so0, &g_w3hi[ga]);
        cp16(st + 4 * TILE_B + so1, &g_w3hi[gb2]);
        cp16(st + 5 * TILE_B + so0, &g_w3lo[ga]);
        cp16(st + 5 * TILE_B + so1, &g_w3lo[gb2]);
    };

    const int m_w = (wid >> 1) * 32, n_w = (wid & 1) * 64;
    const int lmat = lane >> 3, lr = lane & 7;
    const int aRow = m_w + (lmat & 1) * 8 + lr;
    const int aCol = (lmat >> 1) * 8;
    const int bRow = n_w + (lmat >> 1) * 8 + lr;
    const int bCol = (lmat & 1) * 8;

    float acc1[2][8][4], acc2[2][8][4];
#pragma unroll
    for (int mt = 0; mt < 2; mt++)
#pragma unroll
        for (int nt = 0; nt < 8; nt++)
#pragma unroll
            for (int q = 0; q < 4; q++) { acc1[mt][nt][q] = 0.f; acc2[mt][nt][q] = 0.f; }

    load_stage(0, 0);      cp_commit();
    load_stage(1, KT);     cp_commit();

    const int NK = DD / KT;   // 32
    for (int kt = 0; kt < NK; kt++) {
        cp_wait1();
        __syncthreads();
        if (kt + 2 < NK) load_stage((kt + 2) % 3, (kt + 2) * KT);
        cp_commit();
        const u32 st = sb + 512 + (kt % 3) * 6 * TILE_B;
#pragma unroll
        for (int k16 = 0; k16 < KT; k16 += 16) {
            u32 aH[2][4], aL[2][4];
#pragma unroll
            for (int mt = 0; mt < 2; mt++) {
                u32 ao = (u32)((aRow + mt * 16) * PITCH + k16 + aCol) * 2;
                ldsm4(st + ao, aH[mt]);
                ldsm4(st + TILE_B + ao, aL[mt]);
            }
#pragma unroll
            for (int p = 0; p < 4; p++) {
                u32 bo = (u32)((bRow + p * 16) * PITCH + k16 + bCol) * 2;
                u32 b1h[4], b1l[4], b3h[4], b3l[4];
                ldsm4(st + 2 * TILE_B + bo, b1h);
                ldsm4(st + 3 * TILE_B + bo, b1l);
                ldsm4(st + 4 * TILE_B + bo, b3h);
                ldsm4(st + 5 * TILE_B + bo, b3l);
#pragma unroll
                for (int mt = 0; mt < 2; mt++)
#pragma unroll
                    for (int q = 0; q < 2; q++) {
                        int nt = p * 2 + q;
                        mma16816(acc1[mt][nt], aH[mt], &b1h[q * 2]);
                        mma16816(acc1[mt][nt], aH[mt], &b1l[q * 2]);
                        mma16816(acc1[mt][nt], aL[mt], &b1h[q * 2]);
                        mma16816(acc2[mt][nt], aH[mt], &b3h[q * 2]);
                        mma16816(acc2[mt][nt], aH[mt], &b3l[q * 2]);
                        mma16816(acc2[mt][nt], aL[mt], &b3h[q * 2]);
                    }
            }
        }
        __syncthreads();
    }

    // epilogue: silu(h1)*h3 -> bf16 hi/lo -> global
    u32* outHi = (u32*)g_acthi;
    u32* outLo = (u32*)g_actlo;
#pragma unroll
    for (int mt = 0; mt < 2; mt++)
#pragma unroll
        for (int rh = 0; rh < 2; rh++) {
            int rowl = m_w + mt * 16 + rh * 8 + (lane >> 2);
            if (rowl < valid) {
                size_t base = (size_t)(off + mB + rowl) * FF + nf0;
#pragma unroll
                for (int nt = 0; nt < 8; nt++) {
                    float h0 = acc1[mt][nt][rh * 2 + 0];
                    float h1 = acc1[mt][nt][rh * 2 + 1];
                    float a0 = h0 * (1.f / (1.f + __expf(-h0))) * acc2[mt][nt][rh * 2 + 0];
                    float a1 = h1 * (1.f / (1.f + __expf(-h1))) * acc2[mt][nt][rh * 2 + 1];
                    __nv_bfloat162 hh, ll;
                    hh.x = __float2bfloat16(a0); ll.x = __float2bfloat16(a0 - __bfloat162float(hh.x));
                    hh.y = __float2bfloat16(a1); ll.y = __float2bfloat16(a1 - __bfloat162float(hh.y));
                    size_t gi = (base + n_w + nt * 8 + (lane & 3) * 2) >> 1;
                    outHi[gi] = *(u32*)&hh;
                    outLo[gi] = *(u32*)&ll;
                }
            }
        }
}

// ================= GEMM2: out += w * (act @ w2^T), bf16x3 HMMA =================
// 4-stage cp.async pipeline
#define G2_SMEM (512 + 4 * 4 * TILE_B)   // 164352

__global__ void __launch_bounds__(256, 1)
gemm2_mma(float* __restrict__ out) {
    extern __shared__ char smem[];
    const int e   = blockIdx.z;
    const int cnt = g_count[e];
    const int off = g_offset[e];
    const int mB  = blockIdx.y * 128;
    if (mB >= cnt) return;
    const int valid = min(128, cnt - mB);
    const int nd0   = blockIdx.x * 128;
    const int tid   = threadIdx.x;
    const int wid   = tid >> 5, lane = tid & 31;

    const u32 sb = smem_u32(smem);
    const size_t wbase = (size_t)e * DD * FF + (size_t)nd0 * FF;

    const int lrow = tid >> 2, lch = tid & 3;
    const u32 so0 = (u32)(lrow * PITCH + lch * 8) * 2;
    const u32 so1 = (u32)((lrow + 64) * PITCH + lch * 8) * 2;
    const int arow0 = off + mB + min(lrow, valid - 1);
    const int arow1 = off + mB + min(lrow + 64, valid - 1);

    auto load_stage = [&](int s, int k0) {
        u32 st = sb + 512 + s * 4 * TILE_B;
        const size_t aa = (size_t)arow0 * FF + k0 + lch * 8;
        const size_t ab = (size_t)arow1 * FF + k0 + lch * 8;
        cp16(st + so0,          &g_acthi[aa]);
        cp16(st + so1,          &g_acthi[ab]);
        cp16(st + TILE_B + so0, &g_actlo[aa]);
        cp16(st + TILE_B + so1, &g_actlo[ab]);
        const size_t ga  = wbase + (size_t)lrow * FF + k0 + lch * 8;
        const size_t gb2 = wbase + (size_t)(lrow + 64) * FF + k0 + lch * 8;
        cp16(st + 2 * TILE_B + so0, &g_w2hi[ga]);
        cp16(st + 2 * TILE_B + so1, &g_w2hi[gb2]);
        cp16(st + 3 * TILE_B + so0, &g_w2lo[ga]);
        cp16(st + 3 * TILE_B + so1, &g_w2lo[gb2]);
    };

    const int m_w = (wid >> 1) * 32, n_w = (wid & 1) * 64;
    const int lmat = lane >> 3, lr = lane & 7;
    const int aRow = m_w + (lmat & 1) * 8 + lr;
    const int aCol = (lmat >> 1) * 8;
    const int bRow = n_w + (lmat >> 1) * 8 + lr;
    const int bCol = (lmat & 1) * 8;

    float acc[2][8][4];
#pragma unroll
    for (int mt = 0; mt < 2; mt++)
#pragma unroll
        for (int nt = 0; nt < 8; nt++)
#pragma unroll
            for (int q = 0; q < 4; q++) acc[mt][nt][q] = 0.f;

    load_stage(0, 0);      cp_commit();
    load_stage(1, KT);     cp_commit();
    load_stage(2, 2 * KT); cp_commit();

    const int NK = FF / KT;   // 128
    for (int kt = 0; kt < NK; kt++) {
        cp_wait2();
        __syncthreads();
        if (kt + 3 < NK) load_stage((kt + 3) & 3, (kt + 3) * KT);
        cp_commit();
        const u32 st = sb + 512 + (kt & 3) * 4 * TILE_B;
#pragma unroll
        for (int k16 = 0; k16 < KT; k16 += 16) {
            u32 aH[2][4], aL[2][4];
#pragma unroll
            for (int mt = 0; mt < 2; mt++) {
                u32 ao = (u32)((aRow + mt * 16) * PITCH + k16 + aCol) * 2;
                ldsm4(st + ao, aH[mt]);
                ldsm4(st + TILE_B + ao, aL[mt]);
            }
#pragma unroll
            for (int p = 0; p < 4; p++) {
                u32 bo = (u32)((bRow + p * 16) * PITCH + k16 + bCol) * 2;
                u32 bh[4], bl[4];
                ldsm4(st + 2 * TILE_B + bo, bh);
                ldsm4(st + 3 * TILE_B + bo, bl);
#pragma unroll
                for (int mt = 0; mt < 2; mt++)
#pragma unroll
                    for (int q = 0; q < 2; q++) {
                        int nt = p * 2 + q;
                        mma16816(acc[mt][nt], aH[mt], &bh[q * 2]);
                        mma16816(acc[mt][nt], aH[mt], &bl[q * 2]);
                        mma16816(acc[mt][nt], aL[mt], &bh[q * 2]);
                    }
            }
        }
        __syncthreads();
    }

    // epilogue: weighted atomic combine
#pragma unroll
    for (int mt = 0; mt < 2; mt++)
#pragma unroll
        for (int rh = 0; rh < 2; rh++) {
            int rowl = m_w + mt * 16 + rh * 8 + (lane >> 2);
            if (rowl < valid) {
                int gr = off + mB + rowl;
                int tok = g_rowTok[gr];
                float w = g_rowW[gr];
                float* op = &out[(size_t)tok * DD + nd0];
#pragma unroll
                for (int nt = 0; nt < 8; nt++) {
                    int c = n_w + nt * 8 + (lane & 3) * 2;
                    atomicAdd(op + c,     w * acc[mt][nt][rh * 2 + 0]);
                    atomicAdd(op + c + 1, w * acc[mt][nt][rh * 2 + 1]);
                }
            }
        }
}

// ================= host =================
extern "C" void kernel_launch(void* const* d_in, const int* in_sizes, int n_in,
                              void* d_out, int out_size) {
    const float* x  = (const float*)d_in[0];
    const float* gw = (const float*)d_in[1];
    const float* gb = (const float*)d_in[2];
    const float* w1 = (const float*)d_in[3];
    const float* w3 = (const float*)d_in[4];
    const float* w2 = (const float*)d_in[5];
    float* out = (float*)d_out;

    cudaFuncSetAttribute(gemm1_mma, cudaFuncAttributeMaxDynamicSharedMemorySize, G1_SMEM);
    cudaFuncSetAttribute(gemm2_mma, cudaFuncAttributeMaxDynamicSharedMemorySize, G2_SMEM);

    cudaMemsetAsync(out, 0, (size_t)out_size * sizeof(float), 0);

    // fused split (also resets g_count); independent of routing
    const size_t totalChunks = (size_t)XC + 3 * (size_t)WC;
    split_all_kernel<<<(unsigned)((totalChunks + 255) / 256), 256>>>(x, w1, w3, w2);

    router_kernel<<<TT, 128>>>(x, gw, gb);
    scanscatter_kernel<<<1, 256>>>();

    dim3 g1(FF / 128, 32, EE);
    gemm1_mma<<<g1, 256, G1_SMEM>>>();
    dim3 g2(DD / 128, 32, EE);
    gemm2_mma<<<g2, 256, G2_SMEM>>>(out);
}